// round 1
// baseline (speedup 1.0000x reference)
#include <cuda_runtime.h>
#include <math.h>

#define NN 50000
#define NE 800000

// ---------------- scratch (device globals; no allocation allowed) ----------
__device__ float g_h [NN * 256];   // per-layer transformed features
__device__ float g_x1[NN * 256];   // layer-1 output
__device__ float g_x2[NN * 256];   // layer-2 output
__device__ float g_el[NN * 4];
__device__ float g_er[NN * 4];
__device__ float g_eb[NE * 4];     // per-edge e / exp(e-m) scratch (CSR order)
__device__ int   g_deg[NN];
__device__ int   g_off[NN + 1];
__device__ int   g_cur[NN];
__device__ int   g_eidx[NE];
__device__ int   g_bsum[64];

// ---------------- helpers ----------------
__device__ __forceinline__ float warpSum(float v) {
#pragma unroll
    for (int o = 16; o > 0; o >>= 1) v += __shfl_xor_sync(0xffffffffu, v, o);
    return v;
}
__device__ __forceinline__ float warpMax(float v) {
#pragma unroll
    for (int o = 16; o > 0; o >>= 1) v = fmaxf(v, __shfl_xor_sync(0xffffffffu, v, o));
    return v;
}
__device__ __forceinline__ float lrelu(float x) { return x > 0.f ? x : 0.2f * x; }
__device__ __forceinline__ float eluf(float x)  { return x > 0.f ? x : (expf(x) - 1.f); }

// ---------------- CSR build ----------------
__global__ void k_zero_deg() {
    int i = blockIdx.x * blockDim.x + threadIdx.x;
    if (i < NN) g_deg[i] = 0;
}
__global__ void k_hist(const int* __restrict__ dst) {
    int e = blockIdx.x * blockDim.x + threadIdx.x;
    if (e < NE) atomicAdd(&g_deg[dst[e]], 1);
}
__global__ void k_scan1() {
    __shared__ int s[1024];
    int tid = threadIdx.x;
    int i = blockIdx.x * 1024 + tid;
    int v = (i < NN) ? g_deg[i] : 0;
    s[tid] = v;
    __syncthreads();
    for (int o = 1; o < 1024; o <<= 1) {
        int t = (tid >= o) ? s[tid - o] : 0;
        __syncthreads();
        s[tid] += t;
        __syncthreads();
    }
    if (i < NN) g_off[i] = s[tid] - v;               // block-local exclusive
    if (tid == 1023) g_bsum[blockIdx.x] = s[1023];   // block total
}
__global__ void k_scan2() {  // 1 block, 64 threads (49 block sums)
    __shared__ int s[64];
    int tid = threadIdx.x;
    const int nb = (NN + 1023) / 1024;
    int v = (tid < nb) ? g_bsum[tid] : 0;
    s[tid] = v;
    __syncthreads();
    for (int o = 1; o < 64; o <<= 1) {
        int t = (tid >= o) ? s[tid - o] : 0;
        __syncthreads();
        s[tid] += t;
        __syncthreads();
    }
    g_bsum[tid] = s[tid] - v;  // exclusive
}
__global__ void k_scan3() {
    int i = blockIdx.x * blockDim.x + threadIdx.x;
    if (i < NN) {
        int o = g_off[i] + g_bsum[i >> 10];
        g_off[i] = o;
        g_cur[i] = o;
    }
    if (i == 0) g_off[NN] = NE;
}
__global__ void k_fill(const int* __restrict__ dst) {
    int e = blockIdx.x * blockDim.x + threadIdx.x;
    if (e < NE) {
        int p = atomicAdd(&g_cur[dst[e]], 1);
        g_eidx[p] = e;
    }
}

// ---------------- GEMM: C[M,N] = A[M,K] @ B[K,N]; BM=BN=128, BK=8 ----------
__global__ __launch_bounds__(256) void k_gemm(
    const float* __restrict__ A, const float* __restrict__ B,
    float* __restrict__ C, int M, int N, int K) {
    __shared__ float As[8][128];
    __shared__ float Bs[8][128];
    const int tid = threadIdx.x;
    const int row0 = blockIdx.x * 128, col0 = blockIdx.y * 128;
    const int tx = tid & 15, ty = tid >> 4;
    const int arow = tid >> 1, acol = (tid & 1) * 4;
    const int brow = tid >> 5, bcol = (tid & 31) * 4;

    float acc[8][8];
#pragma unroll
    for (int i = 0; i < 8; i++)
#pragma unroll
        for (int j = 0; j < 8; j++) acc[i][j] = 0.f;

    const bool avalid = (row0 + arow) < M;
    for (int k0 = 0; k0 < K; k0 += 8) {
        float4 av = make_float4(0.f, 0.f, 0.f, 0.f);
        if (avalid) av = *(const float4*)(A + (size_t)(row0 + arow) * K + k0 + acol);
        As[acol + 0][arow] = av.x;
        As[acol + 1][arow] = av.y;
        As[acol + 2][arow] = av.z;
        As[acol + 3][arow] = av.w;
        *(float4*)&Bs[brow][bcol] = *(const float4*)(B + (size_t)(k0 + brow) * N + col0 + bcol);
        __syncthreads();
#pragma unroll
        for (int kk = 0; kk < 8; kk++) {
            float a[8], b[8];
            *(float4*)&a[0] = *(const float4*)&As[kk][ty * 8];
            *(float4*)&a[4] = *(const float4*)&As[kk][ty * 8 + 4];
            *(float4*)&b[0] = *(const float4*)&Bs[kk][tx * 8];
            *(float4*)&b[4] = *(const float4*)&Bs[kk][tx * 8 + 4];
#pragma unroll
            for (int i = 0; i < 8; i++)
#pragma unroll
                for (int j = 0; j < 8; j++) acc[i][j] = fmaf(a[i], b[j], acc[i][j]);
        }
        __syncthreads();
    }
#pragma unroll
    for (int i = 0; i < 8; i++) {
        int r = row0 + ty * 8 + i;
        if (r < M) {
            *(float4*)(C + (size_t)r * N + col0 + tx * 8) =
                make_float4(acc[i][0], acc[i][1], acc[i][2], acc[i][3]);
            *(float4*)(C + (size_t)r * N + col0 + tx * 8 + 4) =
                make_float4(acc[i][4], acc[i][5], acc[i][6], acc[i][7]);
        }
    }
}

// ---------------- tiny GEMM for W3 (K=256, N=8): warp per row --------------
__global__ __launch_bounds__(256) void k_gemm_w3(
    const float* __restrict__ A, const float* __restrict__ W, float* __restrict__ C) {
    __shared__ float Ws[256 * 9];
    for (int i = threadIdx.x; i < 2048; i += 256) {
        int k = i >> 3, c = i & 7;
        Ws[k * 9 + c] = W[i];
    }
    __syncthreads();
    int w = (blockIdx.x * blockDim.x + threadIdx.x) >> 5;
    int lane = threadIdx.x & 31;
    if (w >= NN) return;
    float acc[8] = {0.f, 0.f, 0.f, 0.f, 0.f, 0.f, 0.f, 0.f};
    for (int k = lane; k < 256; k += 32) {
        float xv = A[(size_t)w * 256 + k];
#pragma unroll
        for (int c = 0; c < 8; c++) acc[c] = fmaf(xv, Ws[k * 9 + c], acc[c]);
    }
#pragma unroll
    for (int c = 0; c < 8; c++) acc[c] = warpSum(acc[c]);
    if (lane == 0) {
#pragma unroll
        for (int c = 0; c < 8; c++) C[(size_t)w * 8 + c] = acc[c];
    }
}

// ---------------- el/er: warp per node --------------------------------------
template <int H, int D>
__global__ __launch_bounds__(256) void k_eler(
    const float* __restrict__ h, const float* __restrict__ al, const float* __restrict__ ar) {
    int w = (blockIdx.x * blockDim.x + threadIdx.x) >> 5;
    int lane = threadIdx.x & 31;
    if (w >= NN) return;
#pragma unroll
    for (int hh = 0; hh < H; hh++) {
        float sl = 0.f, sr = 0.f;
        for (int d = lane; d < D; d += 32) {
            float v = h[(size_t)w * (H * D) + hh * D + d];
            sl = fmaf(v, al[hh * D + d], sl);
            sr = fmaf(v, ar[hh * D + d], sr);
        }
        sl = warpSum(sl);
        sr = warpSum(sr);
        if (lane == 0) {
            g_el[w * H + hh] = sl;
            g_er[w * H + hh] = sr;
        }
    }
}

// ---------------- GAT aggregate, H=4 D=64 (warp per dst node) ---------------
template <bool ELU>
__global__ __launch_bounds__(256) void k_agg_big(
    const float* __restrict__ h, const int* __restrict__ src,
    const float* __restrict__ bias, float* __restrict__ out) {
    int w = (blockIdx.x * blockDim.x + threadIdx.x) >> 5;
    int lane = threadIdx.x & 31;
    if (w >= NN) return;
    int o0 = g_off[w], o1 = g_off[w + 1];
    int deg = o1 - o0;
    float4 erv = *(const float4*)&g_er[w * 4];

    // pass 1: e = lrelu(el[src]+er[dst]); per-head max
    float m0 = -1e30f, m1 = -1e30f, m2 = -1e30f, m3 = -1e30f;
    for (int i = lane; i < deg; i += 32) {
        int e = g_eidx[o0 + i];
        int s = src[e];
        float4 elv = *(const float4*)&g_el[s * 4];
        float e0 = lrelu(elv.x + erv.x);
        float e1 = lrelu(elv.y + erv.y);
        float e2 = lrelu(elv.z + erv.z);
        float e3 = lrelu(elv.w + erv.w);
        *(float4*)&g_eb[(size_t)(o0 + i) * 4] = make_float4(e0, e1, e2, e3);
        m0 = fmaxf(m0, e0); m1 = fmaxf(m1, e1);
        m2 = fmaxf(m2, e2); m3 = fmaxf(m3, e3);
    }
    m0 = warpMax(m0); m1 = warpMax(m1); m2 = warpMax(m2); m3 = warpMax(m3);

    // pass 2: exp + sum
    float s0 = 0.f, s1 = 0.f, s2 = 0.f, s3 = 0.f;
    for (int i = lane; i < deg; i += 32) {
        float4 ev = *(const float4*)&g_eb[(size_t)(o0 + i) * 4];
        float x0 = expf(ev.x - m0), x1 = expf(ev.y - m1);
        float x2 = expf(ev.z - m2), x3 = expf(ev.w - m3);
        *(float4*)&g_eb[(size_t)(o0 + i) * 4] = make_float4(x0, x1, x2, x3);
        s0 += x0; s1 += x1; s2 += x2; s3 += x3;
    }
    s0 = warpSum(s0); s1 = warpSum(s1); s2 = warpSum(s2); s3 = warpSum(s3);
    float inv0 = 1.f / s0, inv1 = 1.f / s1, inv2 = 1.f / s2, inv3 = 1.f / s3;

    // pass 3: weighted gather; lane owns features [lane*4, +4) and [128+lane*4, +4)
    int hA = lane >> 4;  // head of f0 (0 or 1); head of f1 is hA+2
    float invA = hA ? inv1 : inv0;
    float invB = hA ? inv3 : inv2;
    int f0 = lane * 4, f1 = 128 + lane * 4;
    float4 acc0 = make_float4(0.f, 0.f, 0.f, 0.f);
    float4 acc1 = make_float4(0.f, 0.f, 0.f, 0.f);
    for (int i = 0; i < deg; i++) {
        int e = g_eidx[o0 + i];
        int s = src[e];
        float4 ev = *(const float4*)&g_eb[(size_t)(o0 + i) * 4];
        float aA = (hA ? ev.y : ev.x) * invA;
        float aB = (hA ? ev.w : ev.z) * invB;
        float4 h0 = *(const float4*)&h[(size_t)s * 256 + f0];
        float4 h1 = *(const float4*)&h[(size_t)s * 256 + f1];
        acc0.x = fmaf(aA, h0.x, acc0.x); acc0.y = fmaf(aA, h0.y, acc0.y);
        acc0.z = fmaf(aA, h0.z, acc0.z); acc0.w = fmaf(aA, h0.w, acc0.w);
        acc1.x = fmaf(aB, h1.x, acc1.x); acc1.y = fmaf(aB, h1.y, acc1.y);
        acc1.z = fmaf(aB, h1.z, acc1.z); acc1.w = fmaf(aB, h1.w, acc1.w);
    }
    float4 b0 = *(const float4*)&bias[f0];
    float4 b1 = *(const float4*)&bias[f1];
    acc0.x += b0.x; acc0.y += b0.y; acc0.z += b0.z; acc0.w += b0.w;
    acc1.x += b1.x; acc1.y += b1.y; acc1.z += b1.z; acc1.w += b1.w;
    if (ELU) {
        acc0.x = eluf(acc0.x); acc0.y = eluf(acc0.y); acc0.z = eluf(acc0.z); acc0.w = eluf(acc0.w);
        acc1.x = eluf(acc1.x); acc1.y = eluf(acc1.y); acc1.z = eluf(acc1.z); acc1.w = eluf(acc1.w);
    }
    *(float4*)&out[(size_t)w * 256 + f0] = acc0;
    *(float4*)&out[(size_t)w * 256 + f1] = acc1;
}

// ---------------- GAT aggregate, H=1 D=8 (layer 3) ---------------------------
__global__ __launch_bounds__(256) void k_agg_small(
    const float* __restrict__ h, const int* __restrict__ src,
    const float* __restrict__ bias, float* __restrict__ out) {
    int w = (blockIdx.x * blockDim.x + threadIdx.x) >> 5;
    int lane = threadIdx.x & 31;
    if (w >= NN) return;
    int o0 = g_off[w], o1 = g_off[w + 1];
    int deg = o1 - o0;
    float ern = g_er[w];

    float m = -1e30f;
    for (int i = lane; i < deg; i += 32) {
        int e = g_eidx[o0 + i];
        int s = src[e];
        float v = lrelu(g_el[s] + ern);
        g_eb[o0 + i] = v;
        m = fmaxf(m, v);
    }
    m = warpMax(m);
    float sm = 0.f;
    for (int i = lane; i < deg; i += 32) {
        float x = expf(g_eb[o0 + i] - m);
        g_eb[o0 + i] = x;
        sm += x;
    }
    sm = warpSum(sm);
    float inv = 1.f / sm;

    float acc[8] = {0.f, 0.f, 0.f, 0.f, 0.f, 0.f, 0.f, 0.f};
    for (int i = lane; i < deg; i += 32) {
        int e = g_eidx[o0 + i];
        int s = src[e];
        float a = g_eb[o0 + i] * inv;
        float4 h0 = *(const float4*)&h[(size_t)s * 8];
        float4 h1 = *(const float4*)&h[(size_t)s * 8 + 4];
        acc[0] = fmaf(a, h0.x, acc[0]); acc[1] = fmaf(a, h0.y, acc[1]);
        acc[2] = fmaf(a, h0.z, acc[2]); acc[3] = fmaf(a, h0.w, acc[3]);
        acc[4] = fmaf(a, h1.x, acc[4]); acc[5] = fmaf(a, h1.y, acc[5]);
        acc[6] = fmaf(a, h1.z, acc[6]); acc[7] = fmaf(a, h1.w, acc[7]);
    }
#pragma unroll
    for (int j = 0; j < 8; j++) acc[j] = warpSum(acc[j]);
    if (lane == 0) {
#pragma unroll
        for (int j = 0; j < 8; j++) out[(size_t)w * 8 + j] = acc[j] + bias[j];
    }
}

// ---------------- launch -----------------------------------------------------
extern "C" void kernel_launch(void* const* d_in, const int* in_sizes, int n_in,
                              void* d_out, int out_size) {
    const float* feat = (const float*)d_in[0];
    const int*   src  = (const int*)d_in[1];
    const int*   dst  = (const int*)d_in[2];
    const float* W1 = (const float*)d_in[3];
    const float* al1 = (const float*)d_in[4];
    const float* ar1 = (const float*)d_in[5];
    const float* b1 = (const float*)d_in[6];
    const float* W2 = (const float*)d_in[7];
    const float* al2 = (const float*)d_in[8];
    const float* ar2 = (const float*)d_in[9];
    const float* b2 = (const float*)d_in[10];
    const float* W3 = (const float*)d_in[11];
    const float* al3 = (const float*)d_in[12];
    const float* ar3 = (const float*)d_in[13];
    const float* b3 = (const float*)d_in[14];
    float* out = (float*)d_out;

    void* p;
    cudaGetSymbolAddress(&p, g_h);  float* h  = (float*)p;
    cudaGetSymbolAddress(&p, g_x1); float* x1 = (float*)p;
    cudaGetSymbolAddress(&p, g_x2); float* x2 = (float*)p;

    const int NODE_BLKS = (NN + 255) / 256;       // 196
    const int EDGE_BLKS = (NE + 255) / 256;       // 3125
    const int WARP_BLKS = (NN * 32 + 255) / 256;  // 6250 (warp per node)
    const int SCAN_BLKS = (NN + 1023) / 1024;     // 49

    // CSR by dst (once per call; reused by all 3 layers)
    k_zero_deg<<<NODE_BLKS, 256>>>();
    k_hist<<<EDGE_BLKS, 256>>>(dst);
    k_scan1<<<SCAN_BLKS, 1024>>>();
    k_scan2<<<1, 64>>>();
    k_scan3<<<NODE_BLKS, 256>>>();
    k_fill<<<EDGE_BLKS, 256>>>(dst);

    dim3 g1((NN + 127) / 128, 2);

    // layer 1: 128 -> 4x64
    k_gemm<<<g1, 256>>>(feat, W1, h, NN, 256, 128);
    k_eler<4, 64><<<WARP_BLKS, 256>>>(h, al1, ar1);
    k_agg_big<true><<<WARP_BLKS, 256>>>(h, src, b1, x1);

    // layer 2: 256 -> 4x64
    k_gemm<<<g1, 256>>>(x1, W2, h, NN, 256, 256);
    k_eler<4, 64><<<WARP_BLKS, 256>>>(h, al2, ar2);
    k_agg_big<true><<<WARP_BLKS, 256>>>(h, src, b2, x2);

    // layer 3: 256 -> 1x8, no activation, head-mean == identity (H=1)
    k_gemm_w3<<<WARP_BLKS, 256>>>(x2, W3, h);
    k_eler<1, 8><<<WARP_BLKS, 256>>>(h, al3, ar3);
    k_agg_small<<<WARP_BLKS, 256>>>(h, src, b3, out);
}

// round 2
// speedup vs baseline: 1.0639x; 1.0639x over previous
#include <cuda_runtime.h>
#include <math.h>

#define NN 50000
#define NE 800000

typedef unsigned long long u64;

// ---------------- scratch (device globals; no allocation allowed) ----------
__device__ float g_h [NN * 256];   // per-layer transformed features
__device__ float g_x1[NN * 256];   // layer-1 output
__device__ float g_x2[NN * 256];   // layer-2 output
__device__ float g_el[NN * 4];
__device__ float g_er[NN * 4];
__device__ float g_eb[NE * 4];     // per-edge e / exp(e-m) scratch (CSR order)
__device__ int   g_deg[NN];
__device__ int   g_off[NN + 1];
__device__ int   g_cur[NN];
__device__ int   g_esrc[NE];       // src node id, CSR order (no indirection!)
__device__ int   g_bsum[64];

// ---------------- packed f32x2 helpers ----------------
__device__ __forceinline__ u64 pack2(float x, float y) {
    u64 r; asm("mov.b64 %0, {%1, %2};" : "=l"(r) : "f"(x), "f"(y)); return r;
}
__device__ __forceinline__ u64 ffma2(u64 a, u64 b, u64 c) {
    u64 d; asm("fma.rn.f32x2 %0, %1, %2, %3;" : "=l"(d) : "l"(a), "l"(b), "l"(c));
    return d;
}

// ---------------- helpers ----------------
__device__ __forceinline__ float warpSum(float v) {
#pragma unroll
    for (int o = 16; o > 0; o >>= 1) v += __shfl_xor_sync(0xffffffffu, v, o);
    return v;
}
__device__ __forceinline__ float warpMax(float v) {
#pragma unroll
    for (int o = 16; o > 0; o >>= 1) v = fmaxf(v, __shfl_xor_sync(0xffffffffu, v, o));
    return v;
}
__device__ __forceinline__ float lrelu(float x) { return x > 0.f ? x : 0.2f * x; }
__device__ __forceinline__ float eluf(float x)  { return x > 0.f ? x : (expf(x) - 1.f); }

// ---------------- CSR build ----------------
__global__ void k_zero_deg() {
    int i = blockIdx.x * blockDim.x + threadIdx.x;
    if (i < NN) g_deg[i] = 0;
}
__global__ void k_hist(const int* __restrict__ dst) {
    int e = blockIdx.x * blockDim.x + threadIdx.x;
    if (e < NE) atomicAdd(&g_deg[dst[e]], 1);
}
__global__ void k_scan1() {
    __shared__ int s[1024];
    int tid = threadIdx.x;
    int i = blockIdx.x * 1024 + tid;
    int v = (i < NN) ? g_deg[i] : 0;
    s[tid] = v;
    __syncthreads();
    for (int o = 1; o < 1024; o <<= 1) {
        int t = (tid >= o) ? s[tid - o] : 0;
        __syncthreads();
        s[tid] += t;
        __syncthreads();
    }
    if (i < NN) g_off[i] = s[tid] - v;               // block-local exclusive
    if (tid == 1023) g_bsum[blockIdx.x] = s[1023];   // block total
}
__global__ void k_scan2() {  // 1 block, 64 threads (49 block sums)
    __shared__ int s[64];
    int tid = threadIdx.x;
    const int nb = (NN + 1023) / 1024;
    int v = (tid < nb) ? g_bsum[tid] : 0;
    s[tid] = v;
    __syncthreads();
    for (int o = 1; o < 64; o <<= 1) {
        int t = (tid >= o) ? s[tid - o] : 0;
        __syncthreads();
        s[tid] += t;
        __syncthreads();
    }
    g_bsum[tid] = s[tid] - v;  // exclusive
}
__global__ void k_scan3() {
    int i = blockIdx.x * blockDim.x + threadIdx.x;
    if (i < NN) {
        int o = g_off[i] + g_bsum[i >> 10];
        g_off[i] = o;
        g_cur[i] = o;
    }
    if (i == 0) g_off[NN] = NE;
}
__global__ void k_fill(const int* __restrict__ dst, const int* __restrict__ src) {
    int e = blockIdx.x * blockDim.x + threadIdx.x;
    if (e < NE) {
        int p = atomicAdd(&g_cur[dst[e]], 1);
        g_esrc[p] = src[e];                 // store src id directly, CSR order
    }
}

// ---------------- GEMM: C[M,N] = A[M,K] @ B[K,N]; BM=BN=128, BK=8 ----------
// Inner product done with packed fma.rn.f32x2 (FFMA2): 32 FFMA2 / k-step / thread
__global__ __launch_bounds__(256) void k_gemm(
    const float* __restrict__ A, const float* __restrict__ B,
    float* __restrict__ C, int M, int N, int K) {
    __shared__ float As[8][128];
    __shared__ float Bs[8][128];
    const int tid = threadIdx.x;
    const int row0 = blockIdx.x * 128, col0 = blockIdx.y * 128;
    const int tx = tid & 15, ty = tid >> 4;
    const int arow = tid >> 1, acol = (tid & 1) * 4;
    const int brow = tid >> 5, bcol = (tid & 31) * 4;

    u64 acc[8][4];
#pragma unroll
    for (int i = 0; i < 8; i++)
#pragma unroll
        for (int j = 0; j < 4; j++) acc[i][j] = 0ull;   // (0.f, 0.f)

    const bool avalid = (row0 + arow) < M;
    for (int k0 = 0; k0 < K; k0 += 8) {
        float4 av = make_float4(0.f, 0.f, 0.f, 0.f);
        if (avalid) av = *(const float4*)(A + (size_t)(row0 + arow) * K + k0 + acol);
        As[acol + 0][arow] = av.x;
        As[acol + 1][arow] = av.y;
        As[acol + 2][arow] = av.z;
        As[acol + 3][arow] = av.w;
        *(float4*)&Bs[brow][bcol] = *(const float4*)(B + (size_t)(k0 + brow) * N + col0 + bcol);
        __syncthreads();
#pragma unroll
        for (int kk = 0; kk < 8; kk++) {
            float a[8];
            *(float4*)&a[0] = *(const float4*)&As[kk][ty * 8];
            *(float4*)&a[4] = *(const float4*)&As[kk][ty * 8 + 4];
            // B pairs come straight out of shared as 64-bit lanes
            ulonglong2 bA = *(const ulonglong2*)&Bs[kk][tx * 8];
            ulonglong2 bB = *(const ulonglong2*)&Bs[kk][tx * 8 + 4];
            u64 bb[4] = {bA.x, bA.y, bB.x, bB.y};
            u64 aa[8];
#pragma unroll
            for (int i = 0; i < 8; i++) aa[i] = pack2(a[i], a[i]);
#pragma unroll
            for (int i = 0; i < 8; i++)
#pragma unroll
                for (int j = 0; j < 4; j++) acc[i][j] = ffma2(aa[i], bb[j], acc[i][j]);
        }
        __syncthreads();
    }
#pragma unroll
    for (int i = 0; i < 8; i++) {
        int r = row0 + ty * 8 + i;
        if (r < M) {
            ulonglong2 s0, s1;
            s0.x = acc[i][0]; s0.y = acc[i][1];
            s1.x = acc[i][2]; s1.y = acc[i][3];
            *(ulonglong2*)(C + (size_t)r * N + col0 + tx * 8) = s0;
            *(ulonglong2*)(C + (size_t)r * N + col0 + tx * 8 + 4) = s1;
        }
    }
}

// ---------------- tiny GEMM for W3 (K=256, N=8): warp per row --------------
__global__ __launch_bounds__(256) void k_gemm_w3(
    const float* __restrict__ A, const float* __restrict__ W, float* __restrict__ C) {
    __shared__ float Ws[256 * 9];
    for (int i = threadIdx.x; i < 2048; i += 256) {
        int k = i >> 3, c = i & 7;
        Ws[k * 9 + c] = W[i];
    }
    __syncthreads();
    int w = (blockIdx.x * blockDim.x + threadIdx.x) >> 5;
    int lane = threadIdx.x & 31;
    if (w >= NN) return;
    float acc[8] = {0.f, 0.f, 0.f, 0.f, 0.f, 0.f, 0.f, 0.f};
    for (int k = lane; k < 256; k += 32) {
        float xv = A[(size_t)w * 256 + k];
#pragma unroll
        for (int c = 0; c < 8; c++) acc[c] = fmaf(xv, Ws[k * 9 + c], acc[c]);
    }
#pragma unroll
    for (int c = 0; c < 8; c++) acc[c] = warpSum(acc[c]);
    if (lane == 0) {
#pragma unroll
        for (int c = 0; c < 8; c++) C[(size_t)w * 8 + c] = acc[c];
    }
}

// ---------------- el/er: warp per node --------------------------------------
template <int H, int D>
__global__ __launch_bounds__(256) void k_eler(
    const float* __restrict__ h, const float* __restrict__ al, const float* __restrict__ ar) {
    int w = (blockIdx.x * blockDim.x + threadIdx.x) >> 5;
    int lane = threadIdx.x & 31;
    if (w >= NN) return;
#pragma unroll
    for (int hh = 0; hh < H; hh++) {
        float sl = 0.f, sr = 0.f;
        for (int d = lane; d < D; d += 32) {
            float v = h[(size_t)w * (H * D) + hh * D + d];
            sl = fmaf(v, al[hh * D + d], sl);
            sr = fmaf(v, ar[hh * D + d], sr);
        }
        sl = warpSum(sl);
        sr = warpSum(sr);
        if (lane == 0) {
            g_el[w * H + hh] = sl;
            g_er[w * H + hh] = sr;
        }
    }
}

// ---------------- GAT aggregate, H=4 D=64 (warp per dst node) ---------------
template <bool ELU>
__global__ __launch_bounds__(256) void k_agg_big(
    const float* __restrict__ h,
    const float* __restrict__ bias, float* __restrict__ out) {
    int w = (blockIdx.x * blockDim.x + threadIdx.x) >> 5;
    int lane = threadIdx.x & 31;
    if (w >= NN) return;
    int o0 = g_off[w], o1 = g_off[w + 1];
    int deg = o1 - o0;
    float4 erv = *(const float4*)&g_er[w * 4];

    // pass 1: e = lrelu(el[src]+er[dst]); per-head max
    float m0 = -1e30f, m1 = -1e30f, m2 = -1e30f, m3 = -1e30f;
    for (int i = lane; i < deg; i += 32) {
        int s = g_esrc[o0 + i];
        float4 elv = *(const float4*)&g_el[s * 4];
        float e0 = lrelu(elv.x + erv.x);
        float e1 = lrelu(elv.y + erv.y);
        float e2 = lrelu(elv.z + erv.z);
        float e3 = lrelu(elv.w + erv.w);
        *(float4*)&g_eb[(size_t)(o0 + i) * 4] = make_float4(e0, e1, e2, e3);
        m0 = fmaxf(m0, e0); m1 = fmaxf(m1, e1);
        m2 = fmaxf(m2, e2); m3 = fmaxf(m3, e3);
    }
    m0 = warpMax(m0); m1 = warpMax(m1); m2 = warpMax(m2); m3 = warpMax(m3);

    // pass 2: exp + sum
    float s0 = 0.f, s1 = 0.f, s2 = 0.f, s3 = 0.f;
    for (int i = lane; i < deg; i += 32) {
        float4 ev = *(const float4*)&g_eb[(size_t)(o0 + i) * 4];
        float x0 = expf(ev.x - m0), x1 = expf(ev.y - m1);
        float x2 = expf(ev.z - m2), x3 = expf(ev.w - m3);
        *(float4*)&g_eb[(size_t)(o0 + i) * 4] = make_float4(x0, x1, x2, x3);
        s0 += x0; s1 += x1; s2 += x2; s3 += x3;
    }
    s0 = warpSum(s0); s1 = warpSum(s1); s2 = warpSum(s2); s3 = warpSum(s3);
    float inv0 = 1.f / s0, inv1 = 1.f / s1, inv2 = 1.f / s2, inv3 = 1.f / s3;

    // pass 3: weighted gather; lane owns features [lane*4, +4) and [128+lane*4, +4)
    int hA = lane >> 4;  // head of f0 (0 or 1); head of f1 is hA+2
    float invA = hA ? inv1 : inv0;
    float invB = hA ? inv3 : inv2;
    int f0 = lane * 4, f1 = 128 + lane * 4;
    float4 acc0 = make_float4(0.f, 0.f, 0.f, 0.f);
    float4 acc1 = make_float4(0.f, 0.f, 0.f, 0.f);
    for (int i = 0; i < deg; i++) {
        int s = g_esrc[o0 + i];
        float4 ev = *(const float4*)&g_eb[(size_t)(o0 + i) * 4];
        float aA = (hA ? ev.y : ev.x) * invA;
        float aB = (hA ? ev.w : ev.z) * invB;
        float4 h0 = *(const float4*)&h[(size_t)s * 256 + f0];
        float4 h1 = *(const float4*)&h[(size_t)s * 256 + f1];
        acc0.x = fmaf(aA, h0.x, acc0.x); acc0.y = fmaf(aA, h0.y, acc0.y);
        acc0.z = fmaf(aA, h0.z, acc0.z); acc0.w = fmaf(aA, h0.w, acc0.w);
        acc1.x = fmaf(aB, h1.x, acc1.x); acc1.y = fmaf(aB, h1.y, acc1.y);
        acc1.z = fmaf(aB, h1.z, acc1.z); acc1.w = fmaf(aB, h1.w, acc1.w);
    }
    float4 b0 = *(const float4*)&bias[f0];
    float4 b1 = *(const float4*)&bias[f1];
    acc0.x += b0.x; acc0.y += b0.y; acc0.z += b0.z; acc0.w += b0.w;
    acc1.x += b1.x; acc1.y += b1.y; acc1.z += b1.z; acc1.w += b1.w;
    if (ELU) {
        acc0.x = eluf(acc0.x); acc0.y = eluf(acc0.y); acc0.z = eluf(acc0.z); acc0.w = eluf(acc0.w);
        acc1.x = eluf(acc1.x); acc1.y = eluf(acc1.y); acc1.z = eluf(acc1.z); acc1.w = eluf(acc1.w);
    }
    *(float4*)&out[(size_t)w * 256 + f0] = acc0;
    *(float4*)&out[(size_t)w * 256 + f1] = acc1;
}

// ---------------- GAT aggregate, H=1 D=8 (layer 3) ---------------------------
__global__ __launch_bounds__(256) void k_agg_small(
    const float* __restrict__ h,
    const float* __restrict__ bias, float* __restrict__ out) {
    int w = (blockIdx.x * blockDim.x + threadIdx.x) >> 5;
    int lane = threadIdx.x & 31;
    if (w >= NN) return;
    int o0 = g_off[w], o1 = g_off[w + 1];
    int deg = o1 - o0;
    float ern = g_er[w];

    float m = -1e30f;
    for (int i = lane; i < deg; i += 32) {
        int s = g_esrc[o0 + i];
        float v = lrelu(g_el[s] + ern);
        g_eb[o0 + i] = v;
        m = fmaxf(m, v);
    }
    m = warpMax(m);
    float sm = 0.f;
    for (int i = lane; i < deg; i += 32) {
        float x = expf(g_eb[o0 + i] - m);
        g_eb[o0 + i] = x;
        sm += x;
    }
    sm = warpSum(sm);
    float inv = 1.f / sm;

    float acc[8] = {0.f, 0.f, 0.f, 0.f, 0.f, 0.f, 0.f, 0.f};
    for (int i = lane; i < deg; i += 32) {
        int s = g_esrc[o0 + i];
        float a = g_eb[o0 + i] * inv;
        float4 h0 = *(const float4*)&h[(size_t)s * 8];
        float4 h1 = *(const float4*)&h[(size_t)s * 8 + 4];
        acc[0] = fmaf(a, h0.x, acc[0]); acc[1] = fmaf(a, h0.y, acc[1]);
        acc[2] = fmaf(a, h0.z, acc[2]); acc[3] = fmaf(a, h0.w, acc[3]);
        acc[4] = fmaf(a, h1.x, acc[4]); acc[5] = fmaf(a, h1.y, acc[5]);
        acc[6] = fmaf(a, h1.z, acc[6]); acc[7] = fmaf(a, h1.w, acc[7]);
    }
#pragma unroll
    for (int j = 0; j < 8; j++) acc[j] = warpSum(acc[j]);
    if (lane == 0) {
#pragma unroll
        for (int j = 0; j < 8; j++) out[(size_t)w * 8 + j] = acc[j] + bias[j];
    }
}

// ---------------- launch -----------------------------------------------------
extern "C" void kernel_launch(void* const* d_in, const int* in_sizes, int n_in,
                              void* d_out, int out_size) {
    const float* feat = (const float*)d_in[0];
    const int*   src  = (const int*)d_in[1];
    const int*   dst  = (const int*)d_in[2];
    const float* W1 = (const float*)d_in[3];
    const float* al1 = (const float*)d_in[4];
    const float* ar1 = (const float*)d_in[5];
    const float* b1 = (const float*)d_in[6];
    const float* W2 = (const float*)d_in[7];
    const float* al2 = (const float*)d_in[8];
    const float* ar2 = (const float*)d_in[9];
    const float* b2 = (const float*)d_in[10];
    const float* W3 = (const float*)d_in[11];
    const float* al3 = (const float*)d_in[12];
    const float* ar3 = (const float*)d_in[13];
    const float* b3 = (const float*)d_in[14];
    float* out = (float*)d_out;

    void* p;
    cudaGetSymbolAddress(&p, g_h);  float* h  = (float*)p;
    cudaGetSymbolAddress(&p, g_x1); float* x1 = (float*)p;
    cudaGetSymbolAddress(&p, g_x2); float* x2 = (float*)p;

    const int NODE_BLKS = (NN + 255) / 256;       // 196
    const int EDGE_BLKS = (NE + 255) / 256;       // 3125
    const int WARP_BLKS = (NN * 32 + 255) / 256;  // 6250 (warp per node)
    const int SCAN_BLKS = (NN + 1023) / 1024;     // 49

    // CSR by dst (once per call; reused by all 3 layers)
    k_zero_deg<<<NODE_BLKS, 256>>>();
    k_hist<<<EDGE_BLKS, 256>>>(dst);
    k_scan1<<<SCAN_BLKS, 1024>>>();
    k_scan2<<<1, 64>>>();
    k_scan3<<<NODE_BLKS, 256>>>();
    k_fill<<<EDGE_BLKS, 256>>>(dst, src);

    dim3 g1((NN + 127) / 128, 2);

    // layer 1: 128 -> 4x64
    k_gemm<<<g1, 256>>>(feat, W1, h, NN, 256, 128);
    k_eler<4, 64><<<WARP_BLKS, 256>>>(h, al1, ar1);
    k_agg_big<true><<<WARP_BLKS, 256>>>(h, b1, x1);

    // layer 2: 256 -> 4x64
    k_gemm<<<g1, 256>>>(x1, W2, h, NN, 256, 256);
    k_eler<4, 64><<<WARP_BLKS, 256>>>(h, al2, ar2);
    k_agg_big<true><<<WARP_BLKS, 256>>>(h, b2, x2);

    // layer 3: 256 -> 1x8, no activation, head-mean == identity (H=1)
    k_gemm_w3<<<WARP_BLKS, 256>>>(x2, W3, h);
    k_eler<1, 8><<<WARP_BLKS, 256>>>(h, al3, ar3);
    k_agg_small<<<WARP_BLKS, 256>>>(h, b3, out);
}